// round 12
// baseline (speedup 1.0000x reference)
#include <cuda_runtime.h>
#include <cuda_fp16.h>
#include <math.h>

#define NN 100000
#define EE 1600000
#define DEPTH 4

typedef unsigned int u32;

// ------------------- scratch (device globals; no runtime allocs) -------------------
__device__ float g_P[(size_t)NN * 128];
__device__ float g_hbuf[2][(size_t)NN * 64];
__device__ float g_xbuf[2][(size_t)NN * 3];
__device__ float g_hacc[(size_t)NN * 64];
__device__ float g_xacc[(size_t)NN * 3];
__device__ float g_t[(size_t)NN * 64];
__device__ float g_m[(size_t)EE * 64];
__device__ int   g_deg[NN];
__device__ int   g_off[NN + 1];
__device__ int   g_woff[NN];
__device__ int   g_bsum[256];
__device__ int   g_bscan[256];
__device__ int   g_eidx[EE];
__device__ float g_zero[128];
__device__ __half g_wh[DEPTH * 2 * 4096];
__device__ __half g_wl[DEPTH * 2 * 4096];
__device__ __half g_pwh[DEPTH * 8192];
__device__ __half g_pwl[DEPTH * 8192];
__device__ __half g_n1h[DEPTH * 8192];
__device__ __half g_n1l[DEPTH * 8192];
__device__ __half g_n2h[DEPTH * 4096];
__device__ __half g_n2l[DEPTH * 4096];

// ------------------- helpers -------------------
__device__ __forceinline__ float silu_f(float v) {
    return __fdividef(v, 1.0f + __expf(-v));
}
// paired silu: one RCP for two values (clamped so saturation can't poison the pair)
__device__ __forceinline__ void silu2(float& a, float& b) {
    float ea = fminf(__expf(-a), 1e18f);
    float eb = fminf(__expf(-b), 1e18f);
    float ta = 1.0f + ea, tb = 1.0f + eb;
    float r;
    asm("rcp.approx.f32 %0, %1;" : "=f"(r) : "f"(ta * tb));
    float a2 = a * tb * r;
    float b2 = b * ta * r;
    a = a2; b = b2;
}
__device__ __forceinline__ void red1(float* p, float a) {
    asm volatile("red.global.add.f32 [%0], %1;" :: "l"(p), "f"(a) : "memory");
}
__device__ __forceinline__ u32 smaddr(const void* p) {
    return (u32)__cvta_generic_to_shared(p);
}
__device__ __forceinline__ void ldsm4(u32* r, const void* p) {
    u32 a = smaddr(p);
    asm volatile("ldmatrix.sync.aligned.m8n8.x4.shared.b16 {%0,%1,%2,%3}, [%4];"
                 : "=r"(r[0]), "=r"(r[1]), "=r"(r[2]), "=r"(r[3]) : "r"(a));
}
__device__ __forceinline__ void ldsm4t(u32* r, const void* p) {
    u32 a = smaddr(p);
    asm volatile("ldmatrix.sync.aligned.m8n8.x4.trans.shared.b16 {%0,%1,%2,%3}, [%4];"
                 : "=r"(r[0]), "=r"(r[1]), "=r"(r[2]), "=r"(r[3]) : "r"(a));
}
__device__ __forceinline__ void mma16816(float* c, const u32* a, u32 b0, u32 b1) {
    asm volatile("mma.sync.aligned.m16n8k16.row.col.f32.f16.f16.f32 "
                 "{%0,%1,%2,%3}, {%4,%5,%6,%7}, {%8,%9}, {%0,%1,%2,%3};"
                 : "+f"(c[0]), "+f"(c[1]), "+f"(c[2]), "+f"(c[3])
                 : "r"(a[0]), "r"(a[1]), "r"(a[2]), "r"(a[3]), "r"(b0), "r"(b1));
}
__device__ __forceinline__ void split1(float v, __half& h, __half& l) {
    h = __float2half_rn(v);
    l = __float2half_rn(v - __half2float(h));
}
__device__ __forceinline__ u32 packh2(__half a, __half b) {
    __half2 h = __halves2half2(a, b);
    return *(u32*)&h;
}

// ------------------- weight pre-split: edge (ew2, cw1) -------------------
__global__ void wsplit_kernel(const float* __restrict__ ew2, const float* __restrict__ cw1,
                              __half* __restrict__ wh, __half* __restrict__ wl) {
    int i = blockIdx.x * blockDim.x + threadIdx.x;
    if (i >= DEPTH * 2 * 4096) return;
    int d = i >> 13, which = (i >> 12) & 1, k = i & 4095;
    float v = which ? cw1[d * 4096 + k] : ew2[d * 4096 + k];
    __half h, l; split1(v, h, l);
    wh[i] = h; wl[i] = l;
}

// ------------------- weight pre-split: P / node weights -------------------
__global__ void wsplit2_kernel(const float* __restrict__ ew1, const float* __restrict__ nw1,
                               const float* __restrict__ nw2,
                               __half* __restrict__ pwh, __half* __restrict__ pwl,
                               __half* __restrict__ n1h, __half* __restrict__ n1l,
                               __half* __restrict__ n2h, __half* __restrict__ n2l) {
    int i = blockIdx.x * blockDim.x + threadIdx.x;
    if (i < DEPTH * 8192) {
        int d = i >> 13, r = i & 8191;
        int k = r >> 7, j = r & 127;
        float v = ew1[(size_t)d * 129 * 64 + (size_t)((j < 64) ? k : 64 + k) * 64 + (j & 63)];
        __half h, l; split1(v, h, l);
        pwh[i] = h; pwl[i] = l;
    }
    if (i < DEPTH * 8192) {
        float v = nw1[i];
        __half h, l; split1(v, h, l);
        n1h[i] = h; n1l[i] = l;
    }
    if (i < DEPTH * 4096) {
        float v = nw2[i];
        __half h, l; split1(v, h, l);
        n2h[i] = h; n2l[i] = l;
    }
}

// ------------------- CSR build -------------------
__global__ void deg_zero_kernel(int* __restrict__ deg, float* __restrict__ xacc, int n) {
    int i = blockIdx.x * blockDim.x + threadIdx.x;
    if (i < n) deg[i] = 0;
    if (i < n * 3) xacc[i] = 0.f;
}
__global__ void deg_count_kernel(const int* __restrict__ dst, int* __restrict__ deg, int E) {
    int e = blockIdx.x * blockDim.x + threadIdx.x;
    if (e < E) atomicAdd(&deg[dst[e]], 1);
}
__global__ void scan_blocks_kernel(const int* __restrict__ deg, int* __restrict__ off,
                                   int* __restrict__ bsum, int n) {
    __shared__ int s[512];
    int tid = threadIdx.x;
    int i = blockIdx.x * 512 + tid;
    int v = (i < n) ? deg[i] : 0;
    s[tid] = v;
    __syncthreads();
    for (int d = 1; d < 512; d <<= 1) {
        int t2 = (tid >= d) ? s[tid - d] : 0;
        __syncthreads();
        s[tid] += t2;
        __syncthreads();
    }
    if (i < n) off[i] = s[tid] - v;
    if (tid == 511) bsum[blockIdx.x] = s[511];
}
__global__ void scan_bsums_kernel(const int* __restrict__ bsum, int* __restrict__ bscan, int nb) {
    if (threadIdx.x == 0 && blockIdx.x == 0) {
        int acc = 0;
        for (int b = 0; b < nb; b++) { bscan[b] = acc; acc += bsum[b]; }
    }
}
__global__ void scan_add_kernel(int* __restrict__ off, const int* __restrict__ bscan,
                                int* __restrict__ woff, int n, int Etot) {
    int i = blockIdx.x * blockDim.x + threadIdx.x;
    if (i < n) {
        int v = off[i] + bscan[i >> 9];
        off[i] = v;
        woff[i] = v;
    }
    if (i == 0) off[n] = Etot;
}
__global__ void fill_eidx_kernel(const int* __restrict__ dst, int* __restrict__ woff,
                                 int* __restrict__ eidx, int E) {
    int e = blockIdx.x * blockDim.x + threadIdx.x;
    if (e < E) {
        int p = atomicAdd(&woff[dst[e]], 1);
        eidx[p] = e;
    }
}

// ------------------- generic split-fp16 tensor GEMM -------------------
template<int K, int N, bool ACT>
__global__ __launch_bounds__(128) void tgemm_kernel(
    const float* __restrict__ A1, const float* __restrict__ A2,
    const __half* __restrict__ wh, const __half* __restrict__ wl,
    const float* __restrict__ bias, float* __restrict__ out, int n)
{
    constexpr int SA = K + 8;
    constexpr int SW = N + 8;
    extern __shared__ __half S[];
    __half* sAh = S;
    __half* sAl = S + 64 * SA;
    __half* sWh = S + 2 * 64 * SA;
    __half* sWl = sWh + K * SW;
    float*  s_b = (float*)(sWl + K * SW);

    int t = threadIdx.x, lane = t & 31, w = t >> 5;
    int row0 = blockIdx.x * 64;

    if (t < N) s_b[t] = bias[t];

    for (int idx = t; idx < 64 * (K / 4); idx += 128) {
        int r = idx / (K / 4), c4 = idx % (K / 4);
        int gr = row0 + r;
        float4 v = make_float4(0.f, 0.f, 0.f, 0.f);
        if (gr < n) {
            int c = 4 * c4;
            if (K == 64 || c < 64) v = *(const float4*)(A1 + (size_t)gr * 64 + (c & 63));
            else                   v = *(const float4*)(A2 + (size_t)gr * 64 + (c - 64));
        }
        __half h0,h1,h2,h3,l0,l1,l2,l3;
        split1(v.x,h0,l0); split1(v.y,h1,l1); split1(v.z,h2,l2); split1(v.w,h3,l3);
        *(__half2*)(sAh + r * SA + 4 * c4)     = __halves2half2(h0, h1);
        *(__half2*)(sAh + r * SA + 4 * c4 + 2) = __halves2half2(h2, h3);
        *(__half2*)(sAl + r * SA + 4 * c4)     = __halves2half2(l0, l1);
        *(__half2*)(sAl + r * SA + 4 * c4 + 2) = __halves2half2(l2, l3);
    }
    for (int idx = t; idx < K * (N / 2); idx += 128) {
        int r = idx / (N / 2), c2 = idx % (N / 2);
        ((u32*)(sWh + r * SW))[c2] = ((const u32*)(wh + (size_t)r * N))[c2];
        ((u32*)(sWl + r * SW))[c2] = ((const u32*)(wl + (size_t)r * N))[c2];
    }
    __syncthreads();

    u32 Ah[K / 4], Al[K / 4];
#pragma unroll
    for (int ks = 0; ks < K / 16; ks++) {
        ldsm4(&Ah[4*ks], sAh + (16*w + (lane & 15)) * SA + 16*ks + 8*(lane >> 4));
        ldsm4(&Al[4*ks], sAl + (16*w + (lane & 15)) * SA + 16*ks + 8*(lane >> 4));
    }
    int row = 16 * w + (lane >> 2);
#pragma unroll
    for (int ntp = 0; ntp < N / 16; ntp++) {
        float acc0[4] = {0.f,0.f,0.f,0.f};
        float acc1[4] = {0.f,0.f,0.f,0.f};
#pragma unroll
        for (int ks = 0; ks < K / 16; ks++) {
            u32 bh[4], bl[4];
            ldsm4t(bh, sWh + (16*ks + (lane & 15)) * SW + 8*(2*ntp + (lane >> 4)));
            ldsm4t(bl, sWl + (16*ks + (lane & 15)) * SW + 8*(2*ntp + (lane >> 4)));
            mma16816(acc0, &Ah[4*ks], bh[0], bh[1]);
            mma16816(acc0, &Ah[4*ks], bl[0], bl[1]);
            mma16816(acc0, &Al[4*ks], bh[0], bh[1]);
            mma16816(acc1, &Ah[4*ks], bh[2], bh[3]);
            mma16816(acc1, &Ah[4*ks], bl[2], bl[3]);
            mma16816(acc1, &Al[4*ks], bh[2], bh[3]);
        }
#pragma unroll
        for (int s = 0; s < 2; s++) {
            float* acc = s ? acc1 : acc0;
            int col = 8 * (2*ntp + s) + 2 * (lane & 3);
            float o0 = acc[0] + s_b[col],   o1 = acc[1] + s_b[col+1];
            float o2 = acc[2] + s_b[col],   o3 = acc[3] + s_b[col+1];
            if (ACT) { silu2(o0, o1); silu2(o2, o3); }
            int g0 = row0 + row, g1 = row0 + row + 8;
            if (g0 < n) { float2 v; v.x=o0; v.y=o1; *(float2*)(out + (size_t)g0 * N + col) = v; }
            if (g1 < n) { float2 v; v.x=o2; v.y=o3; *(float2*)(out + (size_t)g1 * N + col) = v; }
        }
    }
}

// ------------------- edge kernel: dst-sorted edge order (via eidx), 256 threads ----
#define HW  (64 * 72)
#define HA  (128 * 72)
template<bool STORE>
__global__ __launch_bounds__(256, 2) void edge_kernel(
    const int* __restrict__ src, const int* __restrict__ dst,
    const int* __restrict__ eidx,
    const float* __restrict__ x, const float* __restrict__ P,
    const float* __restrict__ wr,  const float* __restrict__ eb1,
    const __half* __restrict__ w1h, const __half* __restrict__ w1l,
    const float* __restrict__ eb2,
    const __half* __restrict__ w2h, const __half* __restrict__ w2l,
    const float* __restrict__ cb1, const float* __restrict__ cw2,
    float* __restrict__ mbuf, float* __restrict__ xacc, int E)
{
    extern __shared__ __half S[];
    __half* sW1h = S;
    __half* sW1l = S + HW;
    __half* sW2h = S + 2 * HW;
    __half* sW2l = S + 3 * HW;
    __half* sA1h = S + 4 * HW;
    __half* sA1l = S + 4 * HW + HA;
    float*  F    = (float*)(S + 4 * HW + 2 * HA);
    float* s_wr  = F;
    float* s_eb1 = F + 64;
    float* s_eb2 = F + 128;
    float* s_cb1 = F + 192;
    float* s_cw2 = F + 256;
    float* s_u0  = F + 320;
    float* s_u1  = F + 448;
    float* s_u2  = F + 576;
    float* s_cp  = F + 704;
    int*   s_di  = (int*)(F + 832);

    int t = threadIdx.x;
    int lane = t & 31, w = t >> 5;
    int em0 = blockIdx.x * 128;

    if (t < 64) {
        s_wr[t] = wr[t]; s_eb1[t] = eb1[t]; s_eb2[t] = eb2[t];
        s_cb1[t] = cb1[t]; s_cw2[t] = cw2[t];
    }
    {
        u32* d1h = (u32*)sW1h; u32* d1l = (u32*)sW1l;
        u32* d2h = (u32*)sW2h; u32* d2l = (u32*)sW2l;
        const u32* s1h = (const u32*)w1h; const u32* s1l = (const u32*)w1l;
        const u32* s2h = (const u32*)w2h; const u32* s2l = (const u32*)w2l;
#pragma unroll
        for (int i = t; i < 2048; i += 256) {
            int row = i >> 5, c2 = i & 31;
            d1h[row * 36 + c2] = s1h[row * 32 + c2];
            d1l[row * 36 + c2] = s1l[row * 32 + c2];
            d2h[row * 36 + c2] = s2h[row * 32 + c2];
            d2l[row * 36 + c2] = s2l[row * 32 + c2];
        }
    }
    __syncthreads();

    // ---- phase A: pair of threads handles sorted slot; real edge = eidx[pos] ----
    {
        int eloc = t >> 1, ht = t & 1;
        int pos = em0 + eloc;
        int si = 0, di = 0;
        float r = 0.f, u0 = 0.f, u1 = 0.f, u2 = 0.f;
        if (pos < E) {
            int e = eidx[pos];
            si = src[e]; di = dst[e];
            float dx0 = x[si * 3 + 0] - x[di * 3 + 0];
            float dx1 = x[si * 3 + 1] - x[di * 3 + 1];
            float dx2 = x[si * 3 + 2] - x[di * 3 + 2];
            r = dx0 * dx0 + dx1 * dx1 + dx2 * dx2;
            float inv = __fdividef(1.0f, sqrtf(r) + 1e-30f);
            u0 = dx0 * inv; u1 = dx1 * inv; u2 = dx2 * inv;
        }
        if (ht == 0) {
            s_di[eloc] = di;
            s_u0[eloc] = u0; s_u1[eloc] = u1; s_u2[eloc] = u2;
        }
        const float4* Pa = (const float4*)(P + (size_t)si * 128) + ht * 8;
        const float4* Pb = (const float4*)(P + (size_t)di * 128 + 64) + ht * 8;
        __half* rh = sA1h + eloc * 72 + ht * 32;
        __half* rl = sA1l + eloc * 72 + ht * 32;
#pragma unroll
        for (int i = 0; i < 8; i++) {
            float4 va = Pa[i], vb = Pb[i];
            int f = ht * 32 + 4 * i;
            float v0 = va.x + vb.x + r * s_wr[f+0] + s_eb1[f+0];
            float v1 = va.y + vb.y + r * s_wr[f+1] + s_eb1[f+1];
            float v2 = va.z + vb.z + r * s_wr[f+2] + s_eb1[f+2];
            float v3 = va.w + vb.w + r * s_wr[f+3] + s_eb1[f+3];
            silu2(v0, v1); silu2(v2, v3);
            __half h0,h1,h2,h3,l0,l1,l2,l3;
            split1(v0,h0,l0); split1(v1,h1,l1); split1(v2,h2,l2); split1(v3,h3,l3);
            *(__half2*)(rh + 4*i)     = __halves2half2(h0, h1);
            *(__half2*)(rh + 4*i + 2) = __halves2half2(h2, h3);
            *(__half2*)(rl + 4*i)     = __halves2half2(l0, l1);
            *(__half2*)(rl + 4*i + 2) = __halves2half2(l2, l3);
        }
    }
    __syncthreads();

    // ---- GEMM1: m = silu(m1 @ ew2 + eb2), 3-pass split ----
    u32 Ah[16], Al[16];
#pragma unroll
    for (int ks = 0; ks < 4; ks++) {
        const __half* pa = sA1h + (16 * w + (lane & 15)) * 72 + 16 * ks + 8 * (lane >> 4);
        const __half* pl = sA1l + (16 * w + (lane & 15)) * 72 + 16 * ks + 8 * (lane >> 4);
        ldsm4(&Ah[4 * ks], pa);
        ldsm4(&Al[4 * ks], pl);
    }

    u32 A2h[16], A2l[16];
    int row = 16 * w + (lane >> 2);
#pragma unroll
    for (int ntp = 0; ntp < 4; ntp++) {
        float acc0[4] = {0.f, 0.f, 0.f, 0.f};
        float acc1[4] = {0.f, 0.f, 0.f, 0.f};
#pragma unroll
        for (int ks = 0; ks < 4; ks++) {
            u32 bh[4], bl[4];
            ldsm4t(bh, sW1h + (16 * ks + (lane & 15)) * 72 + 8 * (2 * ntp + (lane >> 4)));
            ldsm4t(bl, sW1l + (16 * ks + (lane & 15)) * 72 + 8 * (2 * ntp + (lane >> 4)));
            mma16816(acc0, &Ah[4 * ks], bh[0], bh[1]);
            mma16816(acc0, &Ah[4 * ks], bl[0], bl[1]);
            mma16816(acc0, &Al[4 * ks], bh[0], bh[1]);
            mma16816(acc1, &Ah[4 * ks], bh[2], bh[3]);
            mma16816(acc1, &Ah[4 * ks], bl[2], bl[3]);
            mma16816(acc1, &Al[4 * ks], bh[2], bh[3]);
        }
#pragma unroll
        for (int s = 0; s < 2; s++) {
            float* acc = s ? acc1 : acc0;
            int nt = 2 * ntp + s;
            int col = 8 * nt + 2 * (lane & 3);
            float m0 = acc[0] + s_eb2[col];
            float m1 = acc[1] + s_eb2[col + 1];
            float m2 = acc[2] + s_eb2[col];
            float m3 = acc[3] + s_eb2[col + 1];
            silu2(m0, m1); silu2(m2, m3);
            if (STORE) {
                int p0 = em0 + row, p1 = em0 + row + 8;
                if (p0 < E) { float2 o; o.x = m0; o.y = m1; *(float2*)(mbuf + (size_t)p0 * 64 + col) = o; }
                if (p1 < E) { float2 o; o.x = m2; o.y = m3; *(float2*)(mbuf + (size_t)p1 * 64 + col) = o; }
            }
            __half h0,h1,h2,h3,l0,l1,l2,l3;
            split1(m0,h0,l0); split1(m1,h1,l1); split1(m2,h2,l2); split1(m3,h3,l3);
            int base = 4 * (nt >> 1) + 2 * (nt & 1);
            A2h[base + 0] = packh2(h0, h1);
            A2h[base + 1] = packh2(h2, h3);
            A2l[base + 0] = packh2(l0, l1);
            A2l[base + 1] = packh2(l2, l3);
        }
    }

    // ---- GEMM2: c1 = silu(m @ cw1 + cb1), 3-pass split; c = c1 . cw2 ----
    float rs0 = 0.f, rs1 = 0.f;
#pragma unroll
    for (int ntp = 0; ntp < 4; ntp++) {
        float acc0[4] = {0.f, 0.f, 0.f, 0.f};
        float acc1[4] = {0.f, 0.f, 0.f, 0.f};
#pragma unroll
        for (int ks = 0; ks < 4; ks++) {
            u32 bh[4], bl[4];
            ldsm4t(bh, sW2h + (16 * ks + (lane & 15)) * 72 + 8 * (2 * ntp + (lane >> 4)));
            ldsm4t(bl, sW2l + (16 * ks + (lane & 15)) * 72 + 8 * (2 * ntp + (lane >> 4)));
            mma16816(acc0, &A2h[4 * ks], bh[0], bh[1]);
            mma16816(acc0, &A2h[4 * ks], bl[0], bl[1]);
            mma16816(acc0, &A2l[4 * ks], bh[0], bh[1]);
            mma16816(acc1, &A2h[4 * ks], bh[2], bh[3]);
            mma16816(acc1, &A2h[4 * ks], bl[2], bl[3]);
            mma16816(acc1, &A2l[4 * ks], bh[2], bh[3]);
        }
#pragma unroll
        for (int s = 0; s < 2; s++) {
            float* acc = s ? acc1 : acc0;
            int col = 8 * (2 * ntp + s) + 2 * (lane & 3);
            float a0 = acc[0] + s_cb1[col], a1 = acc[1] + s_cb1[col + 1];
            float a2 = acc[2] + s_cb1[col], a3 = acc[3] + s_cb1[col + 1];
            silu2(a0, a1); silu2(a2, a3);
            rs0 += a0 * s_cw2[col] + a1 * s_cw2[col + 1];
            rs1 += a2 * s_cw2[col] + a3 * s_cw2[col + 1];
        }
    }
    rs0 += __shfl_xor_sync(0xffffffffu, rs0, 1);
    rs0 += __shfl_xor_sync(0xffffffffu, rs0, 2);
    rs1 += __shfl_xor_sync(0xffffffffu, rs1, 1);
    rs1 += __shfl_xor_sync(0xffffffffu, rs1, 2);
    if ((lane & 3) == 0) {
        s_cp[16 * w + (lane >> 2)]     = rs0;
        s_cp[16 * w + 8 + (lane >> 2)] = rs1;
    }
    __syncthreads();

    if (t < 128) {
        int pos = em0 + t;
        if (pos < E) {
            float c = s_cp[t];
            int di = s_di[t];
            float* xp = xacc + (size_t)di * 3;
            red1(xp + 0, c * s_u0[t]);
            red1(xp + 1, c * s_u1[t]);
            red1(xp + 2, c * s_u2[t]);
        }
    }
}

// ------------------- gather: m stored in dst-sorted order -> contiguous stream ----
__global__ void gather_kernel(const float* __restrict__ m, const int* __restrict__ off,
                              float* __restrict__ hn, int n)
{
    int warp = (blockIdx.x * blockDim.x + threadIdx.x) >> 5;
    int lane = threadIdx.x & 31;
    if (warp >= n) return;
    int b = off[warp], en = off[warp + 1];
    float ax = 0.f, ay = 0.f;
    for (int i = b; i < en; i++) {
        float2 v = ((const float2*)(m + (size_t)i * 64))[lane];
        ax += v.x; ay += v.y;
    }
    float2 o; o.x = ax; o.y = ay;
    ((float2*)(hn + (size_t)warp * 64))[lane] = o;
}

// x update fused with xacc re-zero for next layer
__global__ void xupd_kernel(const float* __restrict__ x, float* __restrict__ xacc,
                            float* __restrict__ out, int n3)
{
    int i = blockIdx.x * blockDim.x + threadIdx.x;
    if (i < n3) {
        out[i] = x[i] + xacc[i];
        xacc[i] = 0.f;
    }
}

// ------------------- launch -------------------
extern "C" void kernel_launch(void* const* d_in, const int* in_sizes, int n_in,
                              void* d_out, int out_size)
{
    const float* h0  = (const float*)d_in[0];
    const float* x0  = (const float*)d_in[1];
    const int*   src = (const int*)d_in[2];
    const int*   dst = (const int*)d_in[3];
    const float* ew1 = (const float*)d_in[4];
    const float* eb1 = (const float*)d_in[5];
    const float* ew2 = (const float*)d_in[6];
    const float* eb2 = (const float*)d_in[7];
    const float* nw1 = (const float*)d_in[8];
    const float* nb1 = (const float*)d_in[9];
    const float* nw2 = (const float*)d_in[10];
    const float* nb2 = (const float*)d_in[11];
    const float* cw1 = (const float*)d_in[12];
    const float* cb1 = (const float*)d_in[13];
    const float* cw2 = (const float*)d_in[14];

    int n = in_sizes[0] / 64;
    int E = in_sizes[2];

    float *P, *hA, *xA, *hacc, *xacc, *tb, *mbuf, *zero;
    int *deg, *off, *woff, *bsum, *bscan, *eidx;
    __half *wh, *wl, *pwh, *pwl, *n1h, *n1l, *n2h, *n2l;
    cudaGetSymbolAddress((void**)&P,    g_P);
    cudaGetSymbolAddress((void**)&hA,   g_hbuf);
    cudaGetSymbolAddress((void**)&xA,   g_xbuf);
    cudaGetSymbolAddress((void**)&hacc, g_hacc);
    cudaGetSymbolAddress((void**)&xacc, g_xacc);
    cudaGetSymbolAddress((void**)&tb,   g_t);
    cudaGetSymbolAddress((void**)&mbuf, g_m);
    cudaGetSymbolAddress((void**)&deg,  g_deg);
    cudaGetSymbolAddress((void**)&off,  g_off);
    cudaGetSymbolAddress((void**)&woff, g_woff);
    cudaGetSymbolAddress((void**)&bsum, g_bsum);
    cudaGetSymbolAddress((void**)&bscan,g_bscan);
    cudaGetSymbolAddress((void**)&eidx, g_eidx);
    cudaGetSymbolAddress((void**)&wh,   g_wh);
    cudaGetSymbolAddress((void**)&wl,   g_wl);
    cudaGetSymbolAddress((void**)&pwh,  g_pwh);
    cudaGetSymbolAddress((void**)&pwl,  g_pwl);
    cudaGetSymbolAddress((void**)&n1h,  g_n1h);
    cudaGetSymbolAddress((void**)&n1l,  g_n1l);
    cudaGetSymbolAddress((void**)&n2h,  g_n2h);
    cudaGetSymbolAddress((void**)&n2l,  g_n2l);
    cudaGetSymbolAddress((void**)&zero, g_zero);

    float* hb[2] = { hA, hA + (size_t)NN * 64 };
    float* xb[2] = { xA, xA + (size_t)NN * 3 };

    const int smE  = (4 * HW + 2 * HA) * 2 + 960 * 4;
    const int smP2 = (2 * 64 * 72 + 2 * 64 * 136) * 2 + 128 * 4;
    const int smN1 = (2 * 64 * 136 + 2 * 128 * 72) * 2 + 64 * 4;
    const int smN2 = (2 * 64 * 72 + 2 * 64 * 72) * 2 + 64 * 4;
    cudaFuncSetAttribute(edge_kernel<true>,  cudaFuncAttributeMaxDynamicSharedMemorySize, smE);
    cudaFuncSetAttribute(edge_kernel<false>, cudaFuncAttributeMaxDynamicSharedMemorySize, smE);
    cudaFuncSetAttribute(tgemm_kernel<64, 128, false>, cudaFuncAttributeMaxDynamicSharedMemorySize, smP2);
    cudaFuncSetAttribute(tgemm_kernel<128, 64, true>,  cudaFuncAttributeMaxDynamicSharedMemorySize, smN1);
    cudaFuncSetAttribute(tgemm_kernel<64, 64, false>,  cudaFuncAttributeMaxDynamicSharedMemorySize, smN2);

    int nb_rows = (n + 63) / 64;
    int eb_blocks = (E + 127) / 128;
    int scan_nb = (n + 511) / 512;

    // ---- CSR build up-front ----
    deg_zero_kernel<<<(n * 3 + 255) / 256, 256>>>(deg, xacc, n);
    deg_count_kernel<<<(E + 255) / 256, 256>>>(dst, deg, E);
    scan_blocks_kernel<<<scan_nb, 512>>>(deg, off, bsum, n);
    scan_bsums_kernel<<<1, 32>>>(bsum, bscan, scan_nb);
    scan_add_kernel<<<(n + 255) / 256, 256>>>(off, bscan, woff, n, E);
    fill_eidx_kernel<<<(E + 255) / 256, 256>>>(dst, woff, eidx, E);
    wsplit_kernel<<<(DEPTH * 2 * 4096 + 255) / 256, 256>>>(ew2, cw1, wh, wl);
    wsplit2_kernel<<<(DEPTH * 8192 + 255) / 256, 256>>>(ew1, nw1, nw2,
                                                        pwh, pwl, n1h, n1l, n2h, n2l);

    for (int d = 0; d < DEPTH; d++) {
        const float* hc = d ? hb[(d - 1) & 1] : h0;
        const float* xc = d ? xb[(d - 1) & 1] : x0;
        float* xo = (d == DEPTH - 1) ? (float*)d_out : xb[d & 1];

        tgemm_kernel<64, 128, false><<<nb_rows, 128, smP2>>>(
            hc, hc, pwh + (size_t)d * 8192, pwl + (size_t)d * 8192, zero, P, n);

        const __half* w1h = wh + (size_t)(2 * d) * 4096;
        const __half* w1l = wl + (size_t)(2 * d) * 4096;
        const __half* w2h = wh + (size_t)(2 * d + 1) * 4096;
        const __half* w2l = wl + (size_t)(2 * d + 1) * 4096;
        const float* wrp = ew1 + (size_t)d * 129 * 64 + 128 * 64;

        if (d < DEPTH - 1) {
            edge_kernel<true><<<eb_blocks, 256, smE>>>(
                src, dst, eidx, xc, P, wrp, eb1 + d * 64,
                w1h, w1l, eb2 + d * 64, w2h, w2l,
                cb1 + d * 64, cw2 + d * 64, mbuf, xacc, E);

            gather_kernel<<<(n * 32 + 255) / 256, 256>>>(mbuf, off, hacc, n);

            tgemm_kernel<128, 64, true><<<nb_rows, 128, smN1>>>(
                hc, hacc, n1h + (size_t)d * 8192, n1l + (size_t)d * 8192,
                nb1 + d * 64, tb, n);
            tgemm_kernel<64, 64, false><<<nb_rows, 128, smN2>>>(
                tb, tb, n2h + (size_t)d * 4096, n2l + (size_t)d * 4096,
                nb2 + d * 64, hb[d & 1], n);
        } else {
            edge_kernel<false><<<eb_blocks, 256, smE>>>(
                src, dst, eidx, xc, P, wrp, eb1 + d * 64,
                w1h, w1l, eb2 + d * 64, w2h, w2l,
                cb1 + d * 64, cw2 + d * 64, mbuf, xacc, E);
        }

        // fused: xo = xc + xacc; xacc = 0 (ready for next layer)
        xupd_kernel<<<(n * 3 + 255) / 256, 256>>>(xc, xacc, xo, n * 3);
    }
}

// round 13
// speedup vs baseline: 1.0089x; 1.0089x over previous
#include <cuda_runtime.h>
#include <cuda_fp16.h>
#include <math.h>

#define NN 100000
#define EE 1600000
#define DEPTH 4

typedef unsigned int u32;

// ------------------- scratch (device globals; no runtime allocs) -------------------
__device__ float g_P[(size_t)NN * 128];
__device__ float g_hbuf[2][(size_t)NN * 64];
__device__ float g_xbuf[2][(size_t)NN * 3];
__device__ float g_hacc[(size_t)NN * 64];
__device__ float g_xacc[(size_t)NN * 3];
__device__ float g_t[(size_t)NN * 64];
__device__ float g_m[(size_t)EE * 64];
__device__ int   g_deg[NN];
__device__ int   g_off[NN + 1];
__device__ int   g_woff[NN];
__device__ int   g_bsum[256];
__device__ int   g_bscan[256];
__device__ int   g_eidx[EE];
__device__ float g_zero[128];
__device__ __half g_wh[DEPTH * 2 * 4096];
__device__ __half g_wl[DEPTH * 2 * 4096];
__device__ __half g_pwh[DEPTH * 8192];
__device__ __half g_pwl[DEPTH * 8192];
__device__ __half g_n1h[DEPTH * 8192];
__device__ __half g_n1l[DEPTH * 8192];
__device__ __half g_n2h[DEPTH * 4096];
__device__ __half g_n2l[DEPTH * 4096];

// ------------------- helpers -------------------
__device__ __forceinline__ float silu_f(float v) {
    return __fdividef(v, 1.0f + __expf(-v));
}
__device__ __forceinline__ void red1(float* p, float a) {
    asm volatile("red.global.add.f32 [%0], %1;" :: "l"(p), "f"(a) : "memory");
}
__device__ __forceinline__ u32 smaddr(const void* p) {
    return (u32)__cvta_generic_to_shared(p);
}
__device__ __forceinline__ void ldsm4(u32* r, const void* p) {
    u32 a = smaddr(p);
    asm volatile("ldmatrix.sync.aligned.m8n8.x4.shared.b16 {%0,%1,%2,%3}, [%4];"
                 : "=r"(r[0]), "=r"(r[1]), "=r"(r[2]), "=r"(r[3]) : "r"(a));
}
__device__ __forceinline__ void ldsm4t(u32* r, const void* p) {
    u32 a = smaddr(p);
    asm volatile("ldmatrix.sync.aligned.m8n8.x4.trans.shared.b16 {%0,%1,%2,%3}, [%4];"
                 : "=r"(r[0]), "=r"(r[1]), "=r"(r[2]), "=r"(r[3]) : "r"(a));
}
__device__ __forceinline__ void mma16816(float* c, const u32* a, u32 b0, u32 b1) {
    asm volatile("mma.sync.aligned.m16n8k16.row.col.f32.f16.f16.f32 "
                 "{%0,%1,%2,%3}, {%4,%5,%6,%7}, {%8,%9}, {%0,%1,%2,%3};"
                 : "+f"(c[0]), "+f"(c[1]), "+f"(c[2]), "+f"(c[3])
                 : "r"(a[0]), "r"(a[1]), "r"(a[2]), "r"(a[3]), "r"(b0), "r"(b1));
}
__device__ __forceinline__ void split1(float v, __half& h, __half& l) {
    h = __float2half_rn(v);
    l = __float2half_rn(v - __half2float(h));
}
__device__ __forceinline__ u32 packh2(__half a, __half b) {
    __half2 h = __halves2half2(a, b);
    return *(u32*)&h;
}

// ------------------- weight pre-split: edge (ew2, cw1) -------------------
__global__ void wsplit_kernel(const float* __restrict__ ew2, const float* __restrict__ cw1,
                              __half* __restrict__ wh, __half* __restrict__ wl) {
    int i = blockIdx.x * blockDim.x + threadIdx.x;
    if (i >= DEPTH * 2 * 4096) return;
    int d = i >> 13, which = (i >> 12) & 1, k = i & 4095;
    float v = which ? cw1[d * 4096 + k] : ew2[d * 4096 + k];
    __half h, l; split1(v, h, l);
    wh[i] = h; wl[i] = l;
}

// ------------------- weight pre-split: P / node weights -------------------
__global__ void wsplit2_kernel(const float* __restrict__ ew1, const float* __restrict__ nw1,
                               const float* __restrict__ nw2,
                               __half* __restrict__ pwh, __half* __restrict__ pwl,
                               __half* __restrict__ n1h, __half* __restrict__ n1l,
                               __half* __restrict__ n2h, __half* __restrict__ n2l) {
    int i = blockIdx.x * blockDim.x + threadIdx.x;
    if (i < DEPTH * 8192) {
        int d = i >> 13, r = i & 8191;
        int k = r >> 7, j = r & 127;
        float v = ew1[(size_t)d * 129 * 64 + (size_t)((j < 64) ? k : 64 + k) * 64 + (j & 63)];
        __half h, l; split1(v, h, l);
        pwh[i] = h; pwl[i] = l;
    }
    if (i < DEPTH * 8192) {
        float v = nw1[i];
        __half h, l; split1(v, h, l);
        n1h[i] = h; n1l[i] = l;
    }
    if (i < DEPTH * 4096) {
        float v = nw2[i];
        __half h, l; split1(v, h, l);
        n2h[i] = h; n2l[i] = l;
    }
}

// ------------------- CSR build -------------------
__global__ void deg_zero_kernel(int* __restrict__ deg, float* __restrict__ xacc, int n) {
    int i = blockIdx.x * blockDim.x + threadIdx.x;
    if (i < n) deg[i] = 0;
    if (i < n * 3) xacc[i] = 0.f;
}
__global__ void deg_count_kernel(const int* __restrict__ dst, int* __restrict__ deg, int E) {
    int e = blockIdx.x * blockDim.x + threadIdx.x;
    if (e < E) atomicAdd(&deg[dst[e]], 1);
}
__global__ void scan_blocks_kernel(const int* __restrict__ deg, int* __restrict__ off,
                                   int* __restrict__ bsum, int n) {
    __shared__ int s[512];
    int tid = threadIdx.x;
    int i = blockIdx.x * 512 + tid;
    int v = (i < n) ? deg[i] : 0;
    s[tid] = v;
    __syncthreads();
    for (int d = 1; d < 512; d <<= 1) {
        int t2 = (tid >= d) ? s[tid - d] : 0;
        __syncthreads();
        s[tid] += t2;
        __syncthreads();
    }
    if (i < n) off[i] = s[tid] - v;
    if (tid == 511) bsum[blockIdx.x] = s[511];
}
__global__ void scan_bsums_kernel(const int* __restrict__ bsum, int* __restrict__ bscan, int nb) {
    if (threadIdx.x == 0 && blockIdx.x == 0) {
        int acc = 0;
        for (int b = 0; b < nb; b++) { bscan[b] = acc; acc += bsum[b]; }
    }
}
__global__ void scan_add_kernel(int* __restrict__ off, const int* __restrict__ bscan,
                                int* __restrict__ woff, int n, int Etot) {
    int i = blockIdx.x * blockDim.x + threadIdx.x;
    if (i < n) {
        int v = off[i] + bscan[i >> 9];
        off[i] = v;
        woff[i] = v;
    }
    if (i == 0) off[n] = Etot;
}
__global__ void fill_eidx_kernel(const int* __restrict__ dst, int* __restrict__ woff,
                                 int* __restrict__ eidx, int E) {
    int e = blockIdx.x * blockDim.x + threadIdx.x;
    if (e < E) {
        int p = atomicAdd(&woff[dst[e]], 1);
        eidx[p] = e;
    }
}

// ------------------- generic split-fp16 tensor GEMM -------------------
template<int K, int N, bool ACT>
__global__ __launch_bounds__(128) void tgemm_kernel(
    const float* __restrict__ A1, const float* __restrict__ A2,
    const __half* __restrict__ wh, const __half* __restrict__ wl,
    const float* __restrict__ bias, float* __restrict__ out, int n)
{
    constexpr int SA = K + 8;
    constexpr int SW = N + 8;
    extern __shared__ __half S[];
    __half* sAh = S;
    __half* sAl = S + 64 * SA;
    __half* sWh = S + 2 * 64 * SA;
    __half* sWl = sWh + K * SW;
    float*  s_b = (float*)(sWl + K * SW);

    int t = threadIdx.x, lane = t & 31, w = t >> 5;
    int row0 = blockIdx.x * 64;

    if (t < N) s_b[t] = bias[t];

    for (int idx = t; idx < 64 * (K / 4); idx += 128) {
        int r = idx / (K / 4), c4 = idx % (K / 4);
        int gr = row0 + r;
        float4 v = make_float4(0.f, 0.f, 0.f, 0.f);
        if (gr < n) {
            int c = 4 * c4;
            if (K == 64 || c < 64) v = *(const float4*)(A1 + (size_t)gr * 64 + (c & 63));
            else                   v = *(const float4*)(A2 + (size_t)gr * 64 + (c - 64));
        }
        __half h0,h1,h2,h3,l0,l1,l2,l3;
        split1(v.x,h0,l0); split1(v.y,h1,l1); split1(v.z,h2,l2); split1(v.w,h3,l3);
        *(__half2*)(sAh + r * SA + 4 * c4)     = __halves2half2(h0, h1);
        *(__half2*)(sAh + r * SA + 4 * c4 + 2) = __halves2half2(h2, h3);
        *(__half2*)(sAl + r * SA + 4 * c4)     = __halves2half2(l0, l1);
        *(__half2*)(sAl + r * SA + 4 * c4 + 2) = __halves2half2(l2, l3);
    }
    for (int idx = t; idx < K * (N / 2); idx += 128) {
        int r = idx / (N / 2), c2 = idx % (N / 2);
        ((u32*)(sWh + r * SW))[c2] = ((const u32*)(wh + (size_t)r * N))[c2];
        ((u32*)(sWl + r * SW))[c2] = ((const u32*)(wl + (size_t)r * N))[c2];
    }
    __syncthreads();

    u32 Ah[K / 4], Al[K / 4];
#pragma unroll
    for (int ks = 0; ks < K / 16; ks++) {
        ldsm4(&Ah[4*ks], sAh + (16*w + (lane & 15)) * SA + 16*ks + 8*(lane >> 4));
        ldsm4(&Al[4*ks], sAl + (16*w + (lane & 15)) * SA + 16*ks + 8*(lane >> 4));
    }
    int row = 16 * w + (lane >> 2);
#pragma unroll
    for (int ntp = 0; ntp < N / 16; ntp++) {
        float acc0[4] = {0.f,0.f,0.f,0.f};
        float acc1[4] = {0.f,0.f,0.f,0.f};
#pragma unroll
        for (int ks = 0; ks < K / 16; ks++) {
            u32 bh[4], bl[4];
            ldsm4t(bh, sWh + (16*ks + (lane & 15)) * SW + 8*(2*ntp + (lane >> 4)));
            ldsm4t(bl, sWl + (16*ks + (lane & 15)) * SW + 8*(2*ntp + (lane >> 4)));
            mma16816(acc0, &Ah[4*ks], bh[0], bh[1]);
            mma16816(acc0, &Ah[4*ks], bl[0], bl[1]);
            mma16816(acc0, &Al[4*ks], bh[0], bh[1]);
            mma16816(acc1, &Ah[4*ks], bh[2], bh[3]);
            mma16816(acc1, &Ah[4*ks], bl[2], bl[3]);
            mma16816(acc1, &Al[4*ks], bh[2], bh[3]);
        }
#pragma unroll
        for (int s = 0; s < 2; s++) {
            float* acc = s ? acc1 : acc0;
            int col = 8 * (2*ntp + s) + 2 * (lane & 3);
            float o0 = acc[0] + s_b[col],   o1 = acc[1] + s_b[col+1];
            float o2 = acc[2] + s_b[col],   o3 = acc[3] + s_b[col+1];
            if (ACT) { o0=silu_f(o0); o1=silu_f(o1); o2=silu_f(o2); o3=silu_f(o3); }
            int g0 = row0 + row, g1 = row0 + row + 8;
            if (g0 < n) { float2 v; v.x=o0; v.y=o1; *(float2*)(out + (size_t)g0 * N + col) = v; }
            if (g1 < n) { float2 v; v.x=o2; v.y=o3; *(float2*)(out + (size_t)g1 * N + col) = v; }
        }
    }
}

// ------------------- edge kernel: dst-sorted edge order (via eidx), 256 threads ----
#define HW  (64 * 72)
#define HA  (128 * 72)
template<bool STORE>
__global__ __launch_bounds__(256, 2) void edge_kernel(
    const int* __restrict__ src, const int* __restrict__ dst,
    const int* __restrict__ eidx,
    const float* __restrict__ x, const float* __restrict__ P,
    const float* __restrict__ wr,  const float* __restrict__ eb1,
    const __half* __restrict__ w1h, const __half* __restrict__ w1l,
    const float* __restrict__ eb2,
    const __half* __restrict__ w2h, const __half* __restrict__ w2l,
    const float* __restrict__ cb1, const float* __restrict__ cw2,
    float* __restrict__ mbuf, float* __restrict__ xacc, int E)
{
    extern __shared__ __half S[];
    __half* sW1h = S;
    __half* sW1l = S + HW;
    __half* sW2h = S + 2 * HW;
    __half* sW2l = S + 3 * HW;
    __half* sA1h = S + 4 * HW;
    __half* sA1l = S + 4 * HW + HA;
    float*  F    = (float*)(S + 4 * HW + 2 * HA);
    float* s_wr  = F;
    float* s_eb1 = F + 64;
    float* s_eb2 = F + 128;
    float* s_cb1 = F + 192;
    float* s_cw2 = F + 256;
    float* s_u0  = F + 320;
    float* s_u1  = F + 448;
    float* s_u2  = F + 576;
    float* s_cp  = F + 704;
    int*   s_di  = (int*)(F + 832);

    int t = threadIdx.x;
    int lane = t & 31, w = t >> 5;
    int em0 = blockIdx.x * 128;

    if (t < 64) {
        s_wr[t] = wr[t]; s_eb1[t] = eb1[t]; s_eb2[t] = eb2[t];
        s_cb1[t] = cb1[t]; s_cw2[t] = cw2[t];
    }
    {
        u32* d1h = (u32*)sW1h; u32* d1l = (u32*)sW1l;
        u32* d2h = (u32*)sW2h; u32* d2l = (u32*)sW2l;
        const u32* s1h = (const u32*)w1h; const u32* s1l = (const u32*)w1l;
        const u32* s2h = (const u32*)w2h; const u32* s2l = (const u32*)w2l;
#pragma unroll
        for (int i = t; i < 2048; i += 256) {
            int row = i >> 5, c2 = i & 31;
            d1h[row * 36 + c2] = s1h[row * 32 + c2];
            d1l[row * 36 + c2] = s1l[row * 32 + c2];
            d2h[row * 36 + c2] = s2h[row * 32 + c2];
            d2l[row * 36 + c2] = s2l[row * 32 + c2];
        }
    }
    __syncthreads();

    // ---- phase A: pair of threads handles sorted slot; real edge = eidx[pos] ----
    {
        int eloc = t >> 1, ht = t & 1;
        int pos = em0 + eloc;
        int si = 0, di = 0;
        float r = 0.f, u0 = 0.f, u1 = 0.f, u2 = 0.f;
        if (pos < E) {
            int e = eidx[pos];
            si = src[e]; di = dst[e];
            float dx0 = x[si * 3 + 0] - x[di * 3 + 0];
            float dx1 = x[si * 3 + 1] - x[di * 3 + 1];
            float dx2 = x[si * 3 + 2] - x[di * 3 + 2];
            r = dx0 * dx0 + dx1 * dx1 + dx2 * dx2;
            float inv = __fdividef(1.0f, sqrtf(r) + 1e-30f);
            u0 = dx0 * inv; u1 = dx1 * inv; u2 = dx2 * inv;
        }
        if (ht == 0) {
            s_di[eloc] = di;
            s_u0[eloc] = u0; s_u1[eloc] = u1; s_u2[eloc] = u2;
        }
        const float4* Pa = (const float4*)(P + (size_t)si * 128) + ht * 8;
        const float4* Pb = (const float4*)(P + (size_t)di * 128 + 64) + ht * 8;
        __half* rh = sA1h + eloc * 72 + ht * 32;
        __half* rl = sA1l + eloc * 72 + ht * 32;
#pragma unroll
        for (int i = 0; i < 8; i++) {
            float4 va = Pa[i], vb = Pb[i];
            int f = ht * 32 + 4 * i;
            float v0 = silu_f(va.x + vb.x + r * s_wr[f+0] + s_eb1[f+0]);
            float v1 = silu_f(va.y + vb.y + r * s_wr[f+1] + s_eb1[f+1]);
            float v2 = silu_f(va.z + vb.z + r * s_wr[f+2] + s_eb1[f+2]);
            float v3 = silu_f(va.w + vb.w + r * s_wr[f+3] + s_eb1[f+3]);
            __half h0,h1,h2,h3,l0,l1,l2,l3;
            split1(v0,h0,l0); split1(v1,h1,l1); split1(v2,h2,l2); split1(v3,h3,l3);
            *(__half2*)(rh + 4*i)     = __halves2half2(h0, h1);
            *(__half2*)(rh + 4*i + 2) = __halves2half2(h2, h3);
            *(__half2*)(rl + 4*i)     = __halves2half2(l0, l1);
            *(__half2*)(rl + 4*i + 2) = __halves2half2(l2, l3);
        }
    }
    __syncthreads();

    // ---- GEMM1: m = silu(m1 @ ew2 + eb2), 3-pass split ----
    u32 Ah[16], Al[16];
#pragma unroll
    for (int ks = 0; ks < 4; ks++) {
        const __half* pa = sA1h + (16 * w + (lane & 15)) * 72 + 16 * ks + 8 * (lane >> 4);
        const __half* pl = sA1l + (16 * w + (lane & 15)) * 72 + 16 * ks + 8 * (lane >> 4);
        ldsm4(&Ah[4 * ks], pa);
        ldsm4(&Al[4 * ks], pl);
    }

    u32 A2h[16], A2l[16];
    int row = 16 * w + (lane >> 2);
#pragma unroll
    for (int ntp = 0; ntp < 4; ntp++) {
        float acc0[4] = {0.f, 0.f, 0.f, 0.f};
        float acc1[4] = {0.f, 0.f, 0.f, 0.f};
#pragma unroll
        for (int ks = 0; ks < 4; ks++) {
            u32 bh[4], bl[4];
            ldsm4t(bh, sW1h + (16 * ks + (lane & 15)) * 72 + 8 * (2 * ntp + (lane >> 4)));
            ldsm4t(bl, sW1l + (16 * ks + (lane & 15)) * 72 + 8 * (2 * ntp + (lane >> 4)));
            mma16816(acc0, &Ah[4 * ks], bh[0], bh[1]);
            mma16816(acc0, &Ah[4 * ks], bl[0], bl[1]);
            mma16816(acc0, &Al[4 * ks], bh[0], bh[1]);
            mma16816(acc1, &Ah[4 * ks], bh[2], bh[3]);
            mma16816(acc1, &Ah[4 * ks], bl[2], bl[3]);
            mma16816(acc1, &Al[4 * ks], bh[2], bh[3]);
        }
#pragma unroll
        for (int s = 0; s < 2; s++) {
            float* acc = s ? acc1 : acc0;
            int nt = 2 * ntp + s;
            int col = 8 * nt + 2 * (lane & 3);
            float m0 = silu_f(acc[0] + s_eb2[col]);
            float m1 = silu_f(acc[1] + s_eb2[col + 1]);
            float m2 = silu_f(acc[2] + s_eb2[col]);
            float m3 = silu_f(acc[3] + s_eb2[col + 1]);
            if (STORE) {
                int p0 = em0 + row, p1 = em0 + row + 8;
                if (p0 < E) { float2 o; o.x = m0; o.y = m1; *(float2*)(mbuf + (size_t)p0 * 64 + col) = o; }
                if (p1 < E) { float2 o; o.x = m2; o.y = m3; *(float2*)(mbuf + (size_t)p1 * 64 + col) = o; }
            }
            __half h0,h1,h2,h3,l0,l1,l2,l3;
            split1(m0,h0,l0); split1(m1,h1,l1); split1(m2,h2,l2); split1(m3,h3,l3);
            int base = 4 * (nt >> 1) + 2 * (nt & 1);
            A2h[base + 0] = packh2(h0, h1);
            A2h[base + 1] = packh2(h2, h3);
            A2l[base + 0] = packh2(l0, l1);
            A2l[base + 1] = packh2(l2, l3);
        }
    }

    // ---- GEMM2: c1 = silu(m @ cw1 + cb1), 3-pass split; c = c1 . cw2 ----
    float rs0 = 0.f, rs1 = 0.f;
#pragma unroll
    for (int ntp = 0; ntp < 4; ntp++) {
        float acc0[4] = {0.f, 0.f, 0.f, 0.f};
        float acc1[4] = {0.f, 0.f, 0.f, 0.f};
#pragma unroll
        for (int ks = 0; ks < 4; ks++) {
            u32 bh[4], bl[4];
            ldsm4t(bh, sW2h + (16 * ks + (lane & 15)) * 72 + 8 * (2 * ntp + (lane >> 4)));
            ldsm4t(bl, sW2l + (16 * ks + (lane & 15)) * 72 + 8 * (2 * ntp + (lane >> 4)));
            mma16816(acc0, &A2h[4 * ks], bh[0], bh[1]);
            mma16816(acc0, &A2h[4 * ks], bl[0], bl[1]);
            mma16816(acc0, &A2l[4 * ks], bh[0], bh[1]);
            mma16816(acc1, &A2h[4 * ks], bh[2], bh[3]);
            mma16816(acc1, &A2h[4 * ks], bl[2], bl[3]);
            mma16816(acc1, &A2l[4 * ks], bh[2], bh[3]);
        }
#pragma unroll
        for (int s = 0; s < 2; s++) {
            float* acc = s ? acc1 : acc0;
            int col = 8 * (2 * ntp + s) + 2 * (lane & 3);
            rs0 += silu_f(acc[0] + s_cb1[col]) * s_cw2[col]
                 + silu_f(acc[1] + s_cb1[col + 1]) * s_cw2[col + 1];
            rs1 += silu_f(acc[2] + s_cb1[col]) * s_cw2[col]
                 + silu_f(acc[3] + s_cb1[col + 1]) * s_cw2[col + 1];
        }
    }
    rs0 += __shfl_xor_sync(0xffffffffu, rs0, 1);
    rs0 += __shfl_xor_sync(0xffffffffu, rs0, 2);
    rs1 += __shfl_xor_sync(0xffffffffu, rs1, 1);
    rs1 += __shfl_xor_sync(0xffffffffu, rs1, 2);
    if ((lane & 3) == 0) {
        s_cp[16 * w + (lane >> 2)]     = rs0;
        s_cp[16 * w + 8 + (lane >> 2)] = rs1;
    }
    __syncthreads();

    if (t < 128) {
        int pos = em0 + t;
        if (pos < E) {
            float c = s_cp[t];
            int di = s_di[t];
            float* xp = xacc + (size_t)di * 3;
            red1(xp + 0, c * s_u0[t]);
            red1(xp + 1, c * s_u1[t]);
            red1(xp + 2, c * s_u2[t]);
        }
    }
}

// ------------------- gather: m stored in dst-sorted order -> contiguous stream ----
__global__ void gather_kernel(const float* __restrict__ m, const int* __restrict__ off,
                              float* __restrict__ hn, int n)
{
    int warp = (blockIdx.x * blockDim.x + threadIdx.x) >> 5;
    int lane = threadIdx.x & 31;
    if (warp >= n) return;
    int b = off[warp], en = off[warp + 1];
    float ax = 0.f, ay = 0.f;
    for (int i = b; i < en; i++) {
        float2 v = ((const float2*)(m + (size_t)i * 64))[lane];
        ax += v.x; ay += v.y;
    }
    float2 o; o.x = ax; o.y = ay;
    ((float2*)(hn + (size_t)warp * 64))[lane] = o;
}

// x update fused with xacc re-zero for next layer
__global__ void xupd_kernel(const float* __restrict__ x, float* __restrict__ xacc,
                            float* __restrict__ out, int n3)
{
    int i = blockIdx.x * blockDim.x + threadIdx.x;
    if (i < n3) {
        out[i] = x[i] + xacc[i];
        xacc[i] = 0.f;
    }
}

// ------------------- launch -------------------
extern "C" void kernel_launch(void* const* d_in, const int* in_sizes, int n_in,
                              void* d_out, int out_size)
{
    const float* h0  = (const float*)d_in[0];
    const float* x0  = (const float*)d_in[1];
    const int*   src = (const int*)d_in[2];
    const int*   dst = (const int*)d_in[3];
    const float* ew1 = (const float*)d_in[4];
    const float* eb1 = (const float*)d_in[5];
    const float* ew2 = (const float*)d_in[6];
    const float* eb2 = (const float*)d_in[7];
    const float* nw1 = (const float*)d_in[8];
    const float* nb1 = (const float*)d_in[9];
    const float* nw2 = (const float*)d_in[10];
    const float* nb2 = (const float*)d_in[11];
    const float* cw1 = (const float*)d_in[12];
    const float* cb1 = (const float*)d_in[13];
    const float* cw2 = (const float*)d_in[14];

    int n = in_sizes[0] / 64;
    int E = in_sizes[2];

    float *P, *hA, *xA, *hacc, *xacc, *tb, *mbuf, *zero;
    int *deg, *off, *woff, *bsum, *bscan, *eidx;
    __half *wh, *wl, *pwh, *pwl, *n1h, *n1l, *n2h, *n2l;
    cudaGetSymbolAddress((void**)&P,    g_P);
    cudaGetSymbolAddress((void**)&hA,   g_hbuf);
    cudaGetSymbolAddress((void**)&xA,   g_xbuf);
    cudaGetSymbolAddress((void**)&hacc, g_hacc);
    cudaGetSymbolAddress((void**)&xacc, g_xacc);
    cudaGetSymbolAddress((void**)&tb,   g_t);
    cudaGetSymbolAddress((void**)&mbuf, g_m);
    cudaGetSymbolAddress((void**)&deg,  g_deg);
    cudaGetSymbolAddress((void**)&off,  g_off);
    cudaGetSymbolAddress((void**)&woff, g_woff);
    cudaGetSymbolAddress((void**)&bsum, g_bsum);
    cudaGetSymbolAddress((void**)&bscan,g_bscan);
    cudaGetSymbolAddress((void**)&eidx, g_eidx);
    cudaGetSymbolAddress((void**)&wh,   g_wh);
    cudaGetSymbolAddress((void**)&wl,   g_wl);
    cudaGetSymbolAddress((void**)&pwh,  g_pwh);
    cudaGetSymbolAddress((void**)&pwl,  g_pwl);
    cudaGetSymbolAddress((void**)&n1h,  g_n1h);
    cudaGetSymbolAddress((void**)&n1l,  g_n1l);
    cudaGetSymbolAddress((void**)&n2h,  g_n2h);
    cudaGetSymbolAddress((void**)&n2l,  g_n2l);
    cudaGetSymbolAddress((void**)&zero, g_zero);

    float* hb[2] = { hA, hA + (size_t)NN * 64 };
    float* xb[2] = { xA, xA + (size_t)NN * 3 };

    const int smE  = (4 * HW + 2 * HA) * 2 + 960 * 4;
    const int smP2 = (2 * 64 * 72 + 2 * 64 * 136) * 2 + 128 * 4;
    const int smN1 = (2 * 64 * 136 + 2 * 128 * 72) * 2 + 64 * 4;
    const int smN2 = (2 * 64 * 72 + 2 * 64 * 72) * 2 + 64 * 4;
    cudaFuncSetAttribute(edge_kernel<true>,  cudaFuncAttributeMaxDynamicSharedMemorySize, smE);
    cudaFuncSetAttribute(edge_kernel<false>, cudaFuncAttributeMaxDynamicSharedMemorySize, smE);
    cudaFuncSetAttribute(tgemm_kernel<64, 128, false>, cudaFuncAttributeMaxDynamicSharedMemorySize, smP2);
    cudaFuncSetAttribute(tgemm_kernel<128, 64, true>,  cudaFuncAttributeMaxDynamicSharedMemorySize, smN1);
    cudaFuncSetAttribute(tgemm_kernel<64, 64, false>,  cudaFuncAttributeMaxDynamicSharedMemorySize, smN2);

    int nb_rows = (n + 63) / 64;
    int eb_blocks = (E + 127) / 128;
    int scan_nb = (n + 511) / 512;

    // ---- CSR build up-front ----
    deg_zero_kernel<<<(n * 3 + 255) / 256, 256>>>(deg, xacc, n);
    deg_count_kernel<<<(E + 255) / 256, 256>>>(dst, deg, E);
    scan_blocks_kernel<<<scan_nb, 512>>>(deg, off, bsum, n);
    scan_bsums_kernel<<<1, 32>>>(bsum, bscan, scan_nb);
    scan_add_kernel<<<(n + 255) / 256, 256>>>(off, bscan, woff, n, E);
    fill_eidx_kernel<<<(E + 255) / 256, 256>>>(dst, woff, eidx, E);
    wsplit_kernel<<<(DEPTH * 2 * 4096 + 255) / 256, 256>>>(ew2, cw1, wh, wl);
    wsplit2_kernel<<<(DEPTH * 8192 + 255) / 256, 256>>>(ew1, nw1, nw2,
                                                        pwh, pwl, n1h, n1l, n2h, n2l);

    for (int d = 0; d < DEPTH; d++) {
        const float* hc = d ? hb[(d - 1) & 1] : h0;
        const float* xc = d ? xb[(d - 1) & 1] : x0;
        float* xo = (d == DEPTH - 1) ? (float*)d_out : xb[d & 1];

        tgemm_kernel<64, 128, false><<<nb_rows, 128, smP2>>>(
            hc, hc, pwh + (size_t)d * 8192, pwl + (size_t)d * 8192, zero, P, n);

        const __half* w1h = wh + (size_t)(2 * d) * 4096;
        const __half* w1l = wl + (size_t)(2 * d) * 4096;
        const __half* w2h = wh + (size_t)(2 * d + 1) * 4096;
        const __half* w2l = wl + (size_t)(2 * d + 1) * 4096;
        const float* wrp = ew1 + (size_t)d * 129 * 64 + 128 * 64;

        if (d < DEPTH - 1) {
            edge_kernel<true><<<eb_blocks, 256, smE>>>(
                src, dst, eidx, xc, P, wrp, eb1 + d * 64,
                w1h, w1l, eb2 + d * 64, w2h, w2l,
                cb1 + d * 64, cw2 + d * 64, mbuf, xacc, E);

            gather_kernel<<<(n * 32 + 255) / 256, 256>>>(mbuf, off, hacc, n);

            tgemm_kernel<128, 64, true><<<nb_rows, 128, smN1>>>(
                hc, hacc, n1h + (size_t)d * 8192, n1l + (size_t)d * 8192,
                nb1 + d * 64, tb, n);
            tgemm_kernel<64, 64, false><<<nb_rows, 128, smN2>>>(
                tb, tb, n2h + (size_t)d * 4096, n2l + (size_t)d * 4096,
                nb2 + d * 64, hb[d & 1], n);
        } else {
            edge_kernel<false><<<eb_blocks, 256, smE>>>(
                src, dst, eidx, xc, P, wrp, eb1 + d * 64,
                w1h, w1l, eb2 + d * 64, w2h, w2l,
                cb1 + d * 64, cw2 + d * 64, mbuf, xacc, E);
        }

        // fused: xo = xc + xacc; xacc = 0 (ready for next layer)
        xupd_kernel<<<(n * 3 + 255) / 256, 256>>>(xc, xacc, xo, n * 3);
    }
}

// round 14
// speedup vs baseline: 1.0972x; 1.0876x over previous
#include <cuda_runtime.h>
#include <cuda_fp16.h>
#include <math.h>

#define NN 100000
#define EE 1600000
#define DEPTH 4

typedef unsigned int u32;

// ------------------- scratch (device globals; no runtime allocs) -------------------
__device__ float g_P[(size_t)NN * 128];
__device__ float g_hbuf[2][(size_t)NN * 64];
__device__ float g_xbuf[2][(size_t)NN * 3];
__device__ float g_hacc[(size_t)NN * 64];
__device__ float g_xacc[(size_t)NN * 3];
__device__ float g_t[(size_t)NN * 64];
__device__ int   g_deg[NN];
__device__ int   g_off[NN + 1];
__device__ int   g_woff[NN];
__device__ int   g_bsum[256];
__device__ int   g_bscan[256];
__device__ int   g_eidx[EE];
__device__ float g_zero[128];
__device__ __half g_wh[DEPTH * 2 * 4096];
__device__ __half g_wl[DEPTH * 2 * 4096];
__device__ __half g_pwh[DEPTH * 8192];
__device__ __half g_pwl[DEPTH * 8192];
__device__ __half g_n1h[DEPTH * 8192];
__device__ __half g_n1l[DEPTH * 8192];
__device__ __half g_n2h[DEPTH * 4096];
__device__ __half g_n2l[DEPTH * 4096];

// ------------------- helpers -------------------
__device__ __forceinline__ float silu_f(float v) {
    return __fdividef(v, 1.0f + __expf(-v));
}
__device__ __forceinline__ void red1(float* p, float a) {
    asm volatile("red.global.add.f32 [%0], %1;" :: "l"(p), "f"(a) : "memory");
}
__device__ __forceinline__ u32 smaddr(const void* p) {
    return (u32)__cvta_generic_to_shared(p);
}
__device__ __forceinline__ void ldsm4(u32* r, const void* p) {
    u32 a = smaddr(p);
    asm volatile("ldmatrix.sync.aligned.m8n8.x4.shared.b16 {%0,%1,%2,%3}, [%4];"
                 : "=r"(r[0]), "=r"(r[1]), "=r"(r[2]), "=r"(r[3]) : "r"(a));
}
__device__ __forceinline__ void ldsm4t(u32* r, const void* p) {
    u32 a = smaddr(p);
    asm volatile("ldmatrix.sync.aligned.m8n8.x4.trans.shared.b16 {%0,%1,%2,%3}, [%4];"
                 : "=r"(r[0]), "=r"(r[1]), "=r"(r[2]), "=r"(r[3]) : "r"(a));
}
__device__ __forceinline__ void mma16816(float* c, const u32* a, u32 b0, u32 b1) {
    asm volatile("mma.sync.aligned.m16n8k16.row.col.f32.f16.f16.f32 "
                 "{%0,%1,%2,%3}, {%4,%5,%6,%7}, {%8,%9}, {%0,%1,%2,%3};"
                 : "+f"(c[0]), "+f"(c[1]), "+f"(c[2]), "+f"(c[3])
                 : "r"(a[0]), "r"(a[1]), "r"(a[2]), "r"(a[3]), "r"(b0), "r"(b1));
}
__device__ __forceinline__ void split1(float v, __half& h, __half& l) {
    h = __float2half_rn(v);
    l = __float2half_rn(v - __half2float(h));
}
__device__ __forceinline__ u32 packh2(__half a, __half b) {
    __half2 h = __halves2half2(a, b);
    return *(u32*)&h;
}

// ------------------- weight pre-split: edge (ew2, cw1) -------------------
__global__ void wsplit_kernel(const float* __restrict__ ew2, const float* __restrict__ cw1,
                              __half* __restrict__ wh, __half* __restrict__ wl) {
    int i = blockIdx.x * blockDim.x + threadIdx.x;
    if (i >= DEPTH * 2 * 4096) return;
    int d = i >> 13, which = (i >> 12) & 1, k = i & 4095;
    float v = which ? cw1[d * 4096 + k] : ew2[d * 4096 + k];
    __half h, l; split1(v, h, l);
    wh[i] = h; wl[i] = l;
}

// ------------------- weight pre-split: P / node weights -------------------
__global__ void wsplit2_kernel(const float* __restrict__ ew1, const float* __restrict__ nw1,
                               const float* __restrict__ nw2,
                               __half* __restrict__ pwh, __half* __restrict__ pwl,
                               __half* __restrict__ n1h, __half* __restrict__ n1l,
                               __half* __restrict__ n2h, __half* __restrict__ n2l) {
    int i = blockIdx.x * blockDim.x + threadIdx.x;
    if (i < DEPTH * 8192) {
        int d = i >> 13, r = i & 8191;
        int k = r >> 7, j = r & 127;
        float v = ew1[(size_t)d * 129 * 64 + (size_t)((j < 64) ? k : 64 + k) * 64 + (j & 63)];
        __half h, l; split1(v, h, l);
        pwh[i] = h; pwl[i] = l;
    }
    if (i < DEPTH * 8192) {
        float v = nw1[i];
        __half h, l; split1(v, h, l);
        n1h[i] = h; n1l[i] = l;
    }
    if (i < DEPTH * 4096) {
        float v = nw2[i];
        __half h, l; split1(v, h, l);
        n2h[i] = h; n2l[i] = l;
    }
}

// ------------------- CSR build -------------------
__global__ void deg_zero_kernel(int* __restrict__ deg, float* __restrict__ xacc, int n) {
    int i = blockIdx.x * blockDim.x + threadIdx.x;
    if (i < n) deg[i] = 0;
    if (i < n * 3) xacc[i] = 0.f;
}
__global__ void deg_count_kernel(const int* __restrict__ dst, int* __restrict__ deg, int E) {
    int e = blockIdx.x * blockDim.x + threadIdx.x;
    if (e < E) atomicAdd(&deg[dst[e]], 1);
}
__global__ void scan_blocks_kernel(const int* __restrict__ deg, int* __restrict__ off,
                                   int* __restrict__ bsum, int n) {
    __shared__ int s[512];
    int tid = threadIdx.x;
    int i = blockIdx.x * 512 + tid;
    int v = (i < n) ? deg[i] : 0;
    s[tid] = v;
    __syncthreads();
    for (int d = 1; d < 512; d <<= 1) {
        int t2 = (tid >= d) ? s[tid - d] : 0;
        __syncthreads();
        s[tid] += t2;
        __syncthreads();
    }
    if (i < n) off[i] = s[tid] - v;
    if (tid == 511) bsum[blockIdx.x] = s[511];
}
__global__ void scan_bsums_kernel(const int* __restrict__ bsum, int* __restrict__ bscan, int nb) {
    if (threadIdx.x == 0 && blockIdx.x == 0) {
        int acc = 0;
        for (int b = 0; b < nb; b++) { bscan[b] = acc; acc += bsum[b]; }
    }
}
__global__ void scan_add_kernel(int* __restrict__ off, const int* __restrict__ bscan,
                                int* __restrict__ woff, int n, int Etot) {
    int i = blockIdx.x * blockDim.x + threadIdx.x;
    if (i < n) {
        int v = off[i] + bscan[i >> 9];
        off[i] = v;
        woff[i] = v;
    }
    if (i == 0) off[n] = Etot;
}
__global__ void fill_eidx_kernel(const int* __restrict__ dst, int* __restrict__ woff,
                                 int* __restrict__ eidx, int E) {
    int e = blockIdx.x * blockDim.x + threadIdx.x;
    if (e < E) {
        int p = atomicAdd(&woff[dst[e]], 1);
        eidx[p] = e;
    }
}
__global__ void zeroh_kernel(float* __restrict__ hacc, int nh) {
    int i = blockIdx.x * blockDim.x + threadIdx.x;
    if (i < nh) hacc[i] = 0.f;
}

// ------------------- generic split-fp16 tensor GEMM -------------------
template<int K, int N, bool ACT>
__global__ __launch_bounds__(128) void tgemm_kernel(
    const float* __restrict__ A1, const float* __restrict__ A2,
    const __half* __restrict__ wh, const __half* __restrict__ wl,
    const float* __restrict__ bias, float* __restrict__ out, int n)
{
    constexpr int SA = K + 8;
    constexpr int SW = N + 8;
    extern __shared__ __half S[];
    __half* sAh = S;
    __half* sAl = S + 64 * SA;
    __half* sWh = S + 2 * 64 * SA;
    __half* sWl = sWh + K * SW;
    float*  s_b = (float*)(sWl + K * SW);

    int t = threadIdx.x, lane = t & 31, w = t >> 5;
    int row0 = blockIdx.x * 64;

    if (t < N) s_b[t] = bias[t];

    for (int idx = t; idx < 64 * (K / 4); idx += 128) {
        int r = idx / (K / 4), c4 = idx % (K / 4);
        int gr = row0 + r;
        float4 v = make_float4(0.f, 0.f, 0.f, 0.f);
        if (gr < n) {
            int c = 4 * c4;
            if (K == 64 || c < 64) v = *(const float4*)(A1 + (size_t)gr * 64 + (c & 63));
            else                   v = *(const float4*)(A2 + (size_t)gr * 64 + (c - 64));
        }
        __half h0,h1,h2,h3,l0,l1,l2,l3;
        split1(v.x,h0,l0); split1(v.y,h1,l1); split1(v.z,h2,l2); split1(v.w,h3,l3);
        *(__half2*)(sAh + r * SA + 4 * c4)     = __halves2half2(h0, h1);
        *(__half2*)(sAh + r * SA + 4 * c4 + 2) = __halves2half2(h2, h3);
        *(__half2*)(sAl + r * SA + 4 * c4)     = __halves2half2(l0, l1);
        *(__half2*)(sAl + r * SA + 4 * c4 + 2) = __halves2half2(l2, l3);
    }
    for (int idx = t; idx < K * (N / 2); idx += 128) {
        int r = idx / (N / 2), c2 = idx % (N / 2);
        ((u32*)(sWh + r * SW))[c2] = ((const u32*)(wh + (size_t)r * N))[c2];
        ((u32*)(sWl + r * SW))[c2] = ((const u32*)(wl + (size_t)r * N))[c2];
    }
    __syncthreads();

    u32 Ah[K / 4], Al[K / 4];
#pragma unroll
    for (int ks = 0; ks < K / 16; ks++) {
        ldsm4(&Ah[4*ks], sAh + (16*w + (lane & 15)) * SA + 16*ks + 8*(lane >> 4));
        ldsm4(&Al[4*ks], sAl + (16*w + (lane & 15)) * SA + 16*ks + 8*(lane >> 4));
    }
    int row = 16 * w + (lane >> 2);
#pragma unroll
    for (int ntp = 0; ntp < N / 16; ntp++) {
        float acc0[4] = {0.f,0.f,0.f,0.f};
        float acc1[4] = {0.f,0.f,0.f,0.f};
#pragma unroll
        for (int ks = 0; ks < K / 16; ks++) {
            u32 bh[4], bl[4];
            ldsm4t(bh, sWh + (16*ks + (lane & 15)) * SW + 8*(2*ntp + (lane >> 4)));
            ldsm4t(bl, sWl + (16*ks + (lane & 15)) * SW + 8*(2*ntp + (lane >> 4)));
            mma16816(acc0, &Ah[4*ks], bh[0], bh[1]);
            mma16816(acc0, &Ah[4*ks], bl[0], bl[1]);
            mma16816(acc0, &Al[4*ks], bh[0], bh[1]);
            mma16816(acc1, &Ah[4*ks], bh[2], bh[3]);
            mma16816(acc1, &Ah[4*ks], bl[2], bl[3]);
            mma16816(acc1, &Al[4*ks], bh[2], bh[3]);
        }
#pragma unroll
        for (int s = 0; s < 2; s++) {
            float* acc = s ? acc1 : acc0;
            int col = 8 * (2*ntp + s) + 2 * (lane & 3);
            float o0 = acc[0] + s_b[col],   o1 = acc[1] + s_b[col+1];
            float o2 = acc[2] + s_b[col],   o3 = acc[3] + s_b[col+1];
            if (ACT) { o0=silu_f(o0); o1=silu_f(o1); o2=silu_f(o2); o3=silu_f(o3); }
            int g0 = row0 + row, g1 = row0 + row + 8;
            if (g0 < n) { float2 v; v.x=o0; v.y=o1; *(float2*)(out + (size_t)g0 * N + col) = v; }
            if (g1 < n) { float2 v; v.x=o2; v.y=o3; *(float2*)(out + (size_t)g1 * N + col) = v; }
        }
    }
}

// ------------------- edge kernel: dst-sorted, fused in-block segmented h-reduction ----
#define HW  (64 * 72)
#define HA  (128 * 72)
#define SM_STRIDE 66
template<bool STORE>
__global__ __launch_bounds__(256, 2) void edge_kernel(
    const int* __restrict__ src, const int* __restrict__ dst,
    const int* __restrict__ eidx,
    const float* __restrict__ x, const float* __restrict__ P,
    const float* __restrict__ wr,  const float* __restrict__ eb1,
    const __half* __restrict__ w1h, const __half* __restrict__ w1l,
    const float* __restrict__ eb2,
    const __half* __restrict__ w2h, const __half* __restrict__ w2l,
    const float* __restrict__ cb1, const float* __restrict__ cw2,
    float* __restrict__ hacc, float* __restrict__ xacc, int E)
{
    extern __shared__ __half S[];
    __half* sW1h = S;
    __half* sW1l = S + HW;
    __half* sW2h = S + 2 * HW;
    __half* sW2l = S + 3 * HW;
    __half* sA1h = S + 4 * HW;
    __half* sA1l = S + 4 * HW + HA;
    float*  sM   = (float*)sA1h;            // reused after A-frag loads: [128][SM_STRIDE]
    float*  F    = (float*)(S + 4 * HW + 2 * HA);
    float* s_wr  = F;
    float* s_eb1 = F + 64;
    float* s_eb2 = F + 128;
    float* s_cb1 = F + 192;
    float* s_cw2 = F + 256;
    float* s_u0  = F + 320;
    float* s_u1  = F + 448;
    float* s_u2  = F + 576;
    float* s_cp  = F + 704;
    int*   s_di  = (int*)(F + 832);
    int*   s_wcnt= (int*)(F + 960);         // 8
    int*   s_run = (int*)(F + 968);         // up to 129
    int*   s_nrun= (int*)(F + 1100);

    int t = threadIdx.x;
    int lane = t & 31, w = t >> 5;
    int em0 = blockIdx.x * 128;

    if (t < 64) {
        s_wr[t] = wr[t]; s_eb1[t] = eb1[t]; s_eb2[t] = eb2[t];
        s_cb1[t] = cb1[t]; s_cw2[t] = cw2[t];
    }
    {
        u32* d1h = (u32*)sW1h; u32* d1l = (u32*)sW1l;
        u32* d2h = (u32*)sW2h; u32* d2l = (u32*)sW2l;
        const u32* s1h = (const u32*)w1h; const u32* s1l = (const u32*)w1l;
        const u32* s2h = (const u32*)w2h; const u32* s2l = (const u32*)w2l;
#pragma unroll
        for (int i = t; i < 2048; i += 256) {
            int row = i >> 5, c2 = i & 31;
            d1h[row * 36 + c2] = s1h[row * 32 + c2];
            d1l[row * 36 + c2] = s1l[row * 32 + c2];
            d2h[row * 36 + c2] = s2h[row * 32 + c2];
            d2l[row * 36 + c2] = s2l[row * 32 + c2];
        }
    }
    __syncthreads();

    // ---- phase A: pair of threads per sorted slot; real edge = eidx[pos] ----
    {
        int eloc = t >> 1, ht = t & 1;
        int pos = em0 + eloc;
        int si = 0, di = 0;
        float r = 0.f, u0 = 0.f, u1 = 0.f, u2 = 0.f;
        if (pos < E) {
            int e = eidx[pos];
            si = src[e]; di = dst[e];
            float dx0 = x[si * 3 + 0] - x[di * 3 + 0];
            float dx1 = x[si * 3 + 1] - x[di * 3 + 1];
            float dx2 = x[si * 3 + 2] - x[di * 3 + 2];
            r = dx0 * dx0 + dx1 * dx1 + dx2 * dx2;
            float inv = __fdividef(1.0f, sqrtf(r) + 1e-30f);
            u0 = dx0 * inv; u1 = dx1 * inv; u2 = dx2 * inv;
        }
        if (ht == 0) {
            s_di[eloc] = di;
            s_u0[eloc] = u0; s_u1[eloc] = u1; s_u2[eloc] = u2;
        }
        const float4* Pa = (const float4*)(P + (size_t)si * 128) + ht * 8;
        const float4* Pb = (const float4*)(P + (size_t)di * 128 + 64) + ht * 8;
        __half* rh = sA1h + eloc * 72 + ht * 32;
        __half* rl = sA1l + eloc * 72 + ht * 32;
#pragma unroll
        for (int i = 0; i < 8; i++) {
            float4 va = Pa[i], vb = Pb[i];
            int f = ht * 32 + 4 * i;
            float v0 = silu_f(va.x + vb.x + r * s_wr[f+0] + s_eb1[f+0]);
            float v1 = silu_f(va.y + vb.y + r * s_wr[f+1] + s_eb1[f+1]);
            float v2 = silu_f(va.z + vb.z + r * s_wr[f+2] + s_eb1[f+2]);
            float v3 = silu_f(va.w + vb.w + r * s_wr[f+3] + s_eb1[f+3]);
            __half h0,h1,h2,h3,l0,l1,l2,l3;
            split1(v0,h0,l0); split1(v1,h1,l1); split1(v2,h2,l2); split1(v3,h3,l3);
            *(__half2*)(rh + 4*i)     = __halves2half2(h0, h1);
            *(__half2*)(rh + 4*i + 2) = __halves2half2(h2, h3);
            *(__half2*)(rl + 4*i)     = __halves2half2(l0, l1);
            *(__half2*)(rl + 4*i + 2) = __halves2half2(l2, l3);
        }
    }
    __syncthreads();

    // ---- GEMM1 A-fragment loads (all warps) ----
    u32 Ah[16], Al[16];
#pragma unroll
    for (int ks = 0; ks < 4; ks++) {
        const __half* pa = sA1h + (16 * w + (lane & 15)) * 72 + 16 * ks + 8 * (lane >> 4);
        const __half* pl = sA1l + (16 * w + (lane & 15)) * 72 + 16 * ks + 8 * (lane >> 4);
        ldsm4(&Ah[4 * ks], pa);
        ldsm4(&Al[4 * ks], pl);
    }
    __syncthreads();   // all A-frags in registers before sM overwrites region

    // ---- GEMM1: m = silu(m1 @ ew2 + eb2), 3-pass split ----
    u32 A2h[16], A2l[16];
    int row = 16 * w + (lane >> 2);
#pragma unroll
    for (int ntp = 0; ntp < 4; ntp++) {
        float acc0[4] = {0.f, 0.f, 0.f, 0.f};
        float acc1[4] = {0.f, 0.f, 0.f, 0.f};
#pragma unroll
        for (int ks = 0; ks < 4; ks++) {
            u32 bh[4], bl[4];
            ldsm4t(bh, sW1h + (16 * ks + (lane & 15)) * 72 + 8 * (2 * ntp + (lane >> 4)));
            ldsm4t(bl, sW1l + (16 * ks + (lane & 15)) * 72 + 8 * (2 * ntp + (lane >> 4)));
            mma16816(acc0, &Ah[4 * ks], bh[0], bh[1]);
            mma16816(acc0, &Ah[4 * ks], bl[0], bl[1]);
            mma16816(acc0, &Al[4 * ks], bh[0], bh[1]);
            mma16816(acc1, &Ah[4 * ks], bh[2], bh[3]);
            mma16816(acc1, &Ah[4 * ks], bl[2], bl[3]);
            mma16816(acc1, &Al[4 * ks], bh[2], bh[3]);
        }
#pragma unroll
        for (int s = 0; s < 2; s++) {
            float* acc = s ? acc1 : acc0;
            int nt = 2 * ntp + s;
            int col = 8 * nt + 2 * (lane & 3);
            float m0 = silu_f(acc[0] + s_eb2[col]);
            float m1 = silu_f(acc[1] + s_eb2[col + 1]);
            float m2 = silu_f(acc[2] + s_eb2[col]);
            float m3 = silu_f(acc[3] + s_eb2[col + 1]);
            if (STORE) {
                float2 o0; o0.x = m0; o0.y = m1;
                float2 o1; o1.x = m2; o1.y = m3;
                *(float2*)(sM + (size_t)row * SM_STRIDE + col)       = o0;
                *(float2*)(sM + (size_t)(row + 8) * SM_STRIDE + col) = o1;
            }
            __half h0,h1,h2,h3,l0,l1,l2,l3;
            split1(m0,h0,l0); split1(m1,h1,l1); split1(m2,h2,l2); split1(m3,h3,l3);
            int base = 4 * (nt >> 1) + 2 * (nt & 1);
            A2h[base + 0] = packh2(h0, h1);
            A2h[base + 1] = packh2(h2, h3);
            A2l[base + 0] = packh2(l0, l1);
            A2l[base + 1] = packh2(l2, l3);
        }
    }

    // ---- GEMM2: c1 = silu(m @ cw1 + cb1), 3-pass split; c = c1 . cw2 ----
    float rs0 = 0.f, rs1 = 0.f;
#pragma unroll
    for (int ntp = 0; ntp < 4; ntp++) {
        float acc0[4] = {0.f, 0.f, 0.f, 0.f};
        float acc1[4] = {0.f, 0.f, 0.f, 0.f};
#pragma unroll
        for (int ks = 0; ks < 4; ks++) {
            u32 bh[4], bl[4];
            ldsm4t(bh, sW2h + (16 * ks + (lane & 15)) * 72 + 8 * (2 * ntp + (lane >> 4)));
            ldsm4t(bl, sW2l + (16 * ks + (lane & 15)) * 72 + 8 * (2 * ntp + (lane >> 4)));
            mma16816(acc0, &A2h[4 * ks], bh[0], bh[1]);
            mma16816(acc0, &A2h[4 * ks], bl[0], bl[1]);
            mma16816(acc0, &A2l[4 * ks], bh[0], bh[1]);
            mma16816(acc1, &A2h[4 * ks], bh[2], bh[3]);
            mma16816(acc1, &A2h[4 * ks], bl[2], bl[3]);
            mma16816(acc1, &A2l[4 * ks], bh[2], bh[3]);
        }
#pragma unroll
        for (int s = 0; s < 2; s++) {
            float* acc = s ? acc1 : acc0;
            int col = 8 * (2 * ntp + s) + 2 * (lane & 3);
            rs0 += silu_f(acc[0] + s_cb1[col]) * s_cw2[col]
                 + silu_f(acc[1] + s_cb1[col + 1]) * s_cw2[col + 1];
            rs1 += silu_f(acc[2] + s_cb1[col]) * s_cw2[col]
                 + silu_f(acc[3] + s_cb1[col + 1]) * s_cw2[col + 1];
        }
    }
    rs0 += __shfl_xor_sync(0xffffffffu, rs0, 1);
    rs0 += __shfl_xor_sync(0xffffffffu, rs0, 2);
    rs1 += __shfl_xor_sync(0xffffffffu, rs1, 1);
    rs1 += __shfl_xor_sync(0xffffffffu, rs1, 2);
    if ((lane & 3) == 0) {
        s_cp[16 * w + (lane >> 2)]     = rs0;
        s_cp[16 * w + 8 + (lane >> 2)] = rs1;
    }
    __syncthreads();   // sM + s_cp + s_di visible

    // ---- x scatter ----
    if (t < 128) {
        int pos = em0 + t;
        if (pos < E) {
            float c = s_cp[t];
            int di = s_di[t];
            float* xp = xacc + (size_t)di * 3;
            red1(xp + 0, c * s_u0[t]);
            red1(xp + 1, c * s_u1[t]);
            red1(xp + 2, c * s_u2[t]);
        }
    }

    // ---- fused segmented reduction of m over same-dst runs -> hacc ----
    if (STORE) {
        int valid = E - em0; if (valid > 128) valid = 128;
        int isStart = 0;
        if (t < valid) isStart = (t == 0) || (s_di[t] != s_di[t - 1]);
        u32 bal = __ballot_sync(0xffffffffu, isStart);
        if (lane == 0) s_wcnt[w] = __popc(bal);
        __syncthreads();
        if (isStart) {
            int rank = __popc(bal & ((1u << lane) - 1u));
            for (int i = 0; i < w; i++) rank += s_wcnt[i];
            s_run[rank] = t;
        }
        if (t == 0) *s_nrun = s_wcnt[0] + s_wcnt[1] + s_wcnt[2] + s_wcnt[3];
        __syncthreads();
        int nrun = *s_nrun;
        for (int r = w; r < nrun; r += 8) {
            int start = s_run[r];
            int end = (r + 1 < nrun) ? s_run[r + 1] : valid;
            int di = s_di[start];
            float a0 = 0.f, a1 = 0.f;
            for (int j = start; j < end; j++) {
                float2 v = *(const float2*)(sM + (size_t)j * SM_STRIDE + 2 * lane);
                a0 += v.x; a1 += v.y;
            }
            float* hp = hacc + (size_t)di * 64 + 2 * lane;
            red1(hp + 0, a0);
            red1(hp + 1, a1);
        }
    }
}

// x update fused with xacc re-zero for next layer
__global__ void xupd_kernel(const float* __restrict__ x, float* __restrict__ xacc,
                            float* __restrict__ out, int n3)
{
    int i = blockIdx.x * blockDim.x + threadIdx.x;
    if (i < n3) {
        out[i] = x[i] + xacc[i];
        xacc[i] = 0.f;
    }
}

// ------------------- launch -------------------
extern "C" void kernel_launch(void* const* d_in, const int* in_sizes, int n_in,
                              void* d_out, int out_size)
{
    const float* h0  = (const float*)d_in[0];
    const float* x0  = (const float*)d_in[1];
    const int*   src = (const int*)d_in[2];
    const int*   dst = (const int*)d_in[3];
    const float* ew1 = (const float*)d_in[4];
    const float* eb1 = (const float*)d_in[5];
    const float* ew2 = (const float*)d_in[6];
    const float* eb2 = (const float*)d_in[7];
    const float* nw1 = (const float*)d_in[8];
    const float* nb1 = (const float*)d_in[9];
    const float* nw2 = (const float*)d_in[10];
    const float* nb2 = (const float*)d_in[11];
    const float* cw1 = (const float*)d_in[12];
    const float* cb1 = (const float*)d_in[13];
    const float* cw2 = (const float*)d_in[14];

    int n = in_sizes[0] / 64;
    int E = in_sizes[2];

    float *P, *hA, *xA, *hacc, *xacc, *tb, *zero;
    int *deg, *off, *woff, *bsum, *bscan, *eidx;
    __half *wh, *wl, *pwh, *pwl, *n1h, *n1l, *n2h, *n2l;
    cudaGetSymbolAddress((void**)&P,    g_P);
    cudaGetSymbolAddress((void**)&hA,   g_hbuf);
    cudaGetSymbolAddress((void**)&xA,   g_xbuf);
    cudaGetSymbolAddress((void**)&hacc, g_hacc);
    cudaGetSymbolAddress((void**)&xacc, g_xacc);
    cudaGetSymbolAddress((void**)&tb,   g_t);
    cudaGetSymbolAddress((void**)&deg,  g_deg);
    cudaGetSymbolAddress((void**)&off,  g_off);
    cudaGetSymbolAddress((void**)&woff, g_woff);
    cudaGetSymbolAddress((void**)&bsum, g_bsum);
    cudaGetSymbolAddress((void**)&bscan,g_bscan);
    cudaGetSymbolAddress((void**)&eidx, g_eidx);
    cudaGetSymbolAddress((void**)&wh,   g_wh);
    cudaGetSymbolAddress((void**)&wl,   g_wl);
    cudaGetSymbolAddress((void**)&pwh,  g_pwh);
    cudaGetSymbolAddress((void**)&pwl,  g_pwl);
    cudaGetSymbolAddress((void**)&n1h,  g_n1h);
    cudaGetSymbolAddress((void**)&n1l,  g_n1l);
    cudaGetSymbolAddress((void**)&n2h,  g_n2h);
    cudaGetSymbolAddress((void**)&n2l,  g_n2l);
    cudaGetSymbolAddress((void**)&zero, g_zero);

    float* hb[2] = { hA, hA + (size_t)NN * 64 };
    float* xb[2] = { xA, xA + (size_t)NN * 3 };

    const int smE  = (4 * HW + 2 * HA) * 2 + 1104 * 4;
    const int smP2 = (2 * 64 * 72 + 2 * 64 * 136) * 2 + 128 * 4;
    const int smN1 = (2 * 64 * 136 + 2 * 128 * 72) * 2 + 64 * 4;
    const int smN2 = (2 * 64 * 72 + 2 * 64 * 72) * 2 + 64 * 4;
    cudaFuncSetAttribute(edge_kernel<true>,  cudaFuncAttributeMaxDynamicSharedMemorySize, smE);
    cudaFuncSetAttribute(edge_kernel<false>, cudaFuncAttributeMaxDynamicSharedMemorySize, smE);
    cudaFuncSetAttribute(tgemm_kernel<64, 128, false>, cudaFuncAttributeMaxDynamicSharedMemorySize, smP2);
    cudaFuncSetAttribute(tgemm_kernel<128, 64, true>,  cudaFuncAttributeMaxDynamicSharedMemorySize, smN1);
    cudaFuncSetAttribute(tgemm_kernel<64, 64, false>,  cudaFuncAttributeMaxDynamicSharedMemorySize, smN2);

    int nb_rows = (n + 63) / 64;
    int eb_blocks = (E + 127) / 128;
    int scan_nb = (n + 511) / 512;

    // ---- CSR build up-front ----
    deg_zero_kernel<<<(n * 3 + 255) / 256, 256>>>(deg, xacc, n);
    deg_count_kernel<<<(E + 255) / 256, 256>>>(dst, deg, E);
    scan_blocks_kernel<<<scan_nb, 512>>>(deg, off, bsum, n);
    scan_bsums_kernel<<<1, 32>>>(bsum, bscan, scan_nb);
    scan_add_kernel<<<(n + 255) / 256, 256>>>(off, bscan, woff, n, E);
    fill_eidx_kernel<<<(E + 255) / 256, 256>>>(dst, woff, eidx, E);
    wsplit_kernel<<<(DEPTH * 2 * 4096 + 255) / 256, 256>>>(ew2, cw1, wh, wl);
    wsplit2_kernel<<<(DEPTH * 8192 + 255) / 256, 256>>>(ew1, nw1, nw2,
                                                        pwh, pwl, n1h, n1l, n2h, n2l);

    for (int d = 0; d < DEPTH; d++) {
        const float* hc = d ? hb[(d - 1) & 1] : h0;
        const float* xc = d ? xb[(d - 1) & 1] : x0;
        float* xo = (d == DEPTH - 1) ? (float*)d_out : xb[d & 1];

        tgemm_kernel<64, 128, false><<<nb_rows, 128, smP2>>>(
            hc, hc, pwh + (size_t)d * 8192, pwl + (size_t)d * 8192, zero, P, n);

        const __half* w1h = wh + (size_t)(2 * d) * 4096;
        const __half* w1l = wl + (size_t)(2 * d) * 4096;
        const __half* w2h = wh + (size_t)(2 * d + 1) * 4096;
        const __half* w2l = wl + (size_t)(2 * d + 1) * 4096;
        const float* wrp = ew1 + (size_t)d * 129 * 64 + 128 * 64;

        if (d < DEPTH - 1) {
            zeroh_kernel<<<(n * 64 + 255) / 256, 256>>>(hacc, n * 64);

            edge_kernel<true><<<eb_blocks, 256, smE>>>(
                src, dst, eidx, xc, P, wrp, eb1 + d * 64,
                w1h, w1l, eb2 + d * 64, w2h, w2l,
                cb1 + d * 64, cw2 + d * 64, hacc, xacc, E);

            tgemm_kernel<128, 64, true><<<nb_rows, 128, smN1>>>(
                hc, hacc, n1h + (size_t)d * 8192, n1l + (size_t)d * 8192,
                nb1 + d * 64, tb, n);
            tgemm_kernel<64, 64, false><<<nb_rows, 128, smN2>>>(
                tb, tb, n2h + (size_t)d * 4096, n2l + (size_t)d * 4096,
                nb2 + d * 64, hb[d & 1], n);
        } else {
            edge_kernel<false><<<eb_blocks, 256, smE>>>(
                src, dst, eidx, xc, P, wrp, eb1 + d * 64,
                w1h, w1l, eb2 + d * 64, w2h, w2l,
                cb1 + d * 64, cw2 + d * 64, hacc, xacc, E);
        }

        xupd_kernel<<<(n * 3 + 255) / 256, 256>>>(xc, xacc, xo, n * 3);
    }
}